// round 7
// baseline (speedup 1.0000x reference)
#include <cuda_runtime.h>

#define H   64
#define NH  4
#define MA  64
#define BS  64
#define E   256    // H*NH
#define MAXROWS 4096

// scratch (device globals: no allocation allowed)
// P layout for u rows: element e (l=e&31, k=e>>5) stored at
//   p = (k>>2)*128 + 4*l + (k&3)
// so lane l's 8 elements are two float4s at quads l and 32+l (conflict-free LDS).
__device__ float g_u[MAXROWS * E];
__device__ float g_molpart[BS * 4 * H];  // per-(b,quarter) molecule partials
__device__ int   g_count[BS];            // arrival counters (reset by kA each call)

__device__ __forceinline__ long long scope_at(const void* sp, int i, bool is64) {
    return is64 ? ((const long long*)sp)[i] : (long long)((const int*)sp)[i];
}
__device__ __forceinline__ bool scope_is64(const void* sp) {
    // scope flat: [1, 2, ...]; int32 -> word1 == 2 ; int64 -> word1 == 0
    return ((const int*)sp)[1] == 0;
}
__device__ __forceinline__ float sigmoid_fast(float s) {
    float t;
    asm("tanh.approx.f32 %0, %1;" : "=f"(t) : "f"(0.5f * s));
    return fmaf(0.5f, t, 0.5f);   // 0.5*(1+tanh(s/2)) == sigmoid(s)
}
__device__ __forceinline__ unsigned long long pack2(float x) {
    unsigned r = __float_as_uint(x);
    unsigned long long o;
    asm("mov.b64 %0, {%1, %1};" : "=l"(o) : "r"(r));
    return o;
}
#define FMA2(acc, a, b) asm("fma.rn.f32x2 %0, %1, %2, %0;" : "+l"(acc) : "l"(a), "l"(b))
#define ADD2(dst, a, b) asm("add.rn.f32x2 %0, %1, %2;" : "=l"(dst) : "l"(a), "l"(b))

// ---------------------------------------------------------------------------
// Kernel A: u_flat = inputs @ Wa_pair over N+1 flat rows, P-layout store.
// Wa_pair staged in smem. 8 rows/block. Zeroes flat row 0 + arrival counters.
// dyn smem: wa_s[64*256] + cs[8*64] = 67.5 KB
// ---------------------------------------------------------------------------
__global__ void __launch_bounds__(256) kA(const float* __restrict__ inputs,
                                          const float* __restrict__ Wa_pair,
                                          int n1, float* __restrict__ d_out) {
    extern __shared__ float sm[];
    float* wa_s = sm;            // 64 x 256 (row-major, logical)
    float* cs   = sm + H * E;    // 8 x 64
    const int t = threadIdx.x, blk = blockIdx.x;

    if (blk == 0) {
        if (t < 16)   // flat row 0 = pad row -> zeros
            ((float4*)(d_out + BS * H))[t] = make_float4(0.f, 0.f, 0.f, 0.f);
        if (t < BS) g_count[t] = 0;
    }

    // stage Wa_pair: 4096 float4, straight copy
#pragma unroll
    for (int it = 0; it < 16; it++)
        ((float4*)wa_s)[t + 256 * it] = __ldg(((const float4*)Wa_pair) + t + 256 * it);

    // stage 8 input rows (128 float4)
    if (t < 128) {
        int r = blk * 8 + (t >> 4), q = t & 15;
        float4 z = make_float4(0.f, 0.f, 0.f, 0.f);
        ((float4*)cs)[t] = (r < n1) ? ((const float4*)(inputs + (size_t)r * H))[q] : z;
    }
    __syncthreads();

    const int eg = t & 63, rg = t >> 6;   // 4 e-cols, 2 rows per thread
    const int e0 = eg * 4;
    float4 acc0 = make_float4(0.f, 0.f, 0.f, 0.f);
    float4 acc1 = make_float4(0.f, 0.f, 0.f, 0.f);

#pragma unroll 8
    for (int h = 0; h < H; h++) {
        float4 w = *(const float4*)(wa_s + h * E + e0);
        float c0 = cs[(rg * 2 + 0) * H + h];
        float c1 = cs[(rg * 2 + 1) * H + h];
        acc0.x = fmaf(c0, w.x, acc0.x);  acc0.y = fmaf(c0, w.y, acc0.y);
        acc0.z = fmaf(c0, w.z, acc0.z);  acc0.w = fmaf(c0, w.w, acc0.w);
        acc1.x = fmaf(c1, w.x, acc1.x);  acc1.y = fmaf(c1, w.y, acc1.y);
        acc1.z = fmaf(c1, w.z, acc1.z);  acc1.w = fmaf(c1, w.w, acc1.w);
    }

    float4 av[2] = {acc0, acc1};
#pragma unroll
    for (int m = 0; m < 2; m++) {
        int rr = blk * 8 + rg * 2 + m;
        if (rr < n1) {
            float* dst = g_u + (size_t)rr * E;
            float a4[4] = {av[m].x, av[m].y, av[m].z, av[m].w};
#pragma unroll
            for (int c = 0; c < 4; c++) {
                int e = e0 + c;
                int l = e & 31, k = e >> 5;
                dst[(k >> 2) * 128 + 4 * l + (k & 3)] = a4[c];
            }
        }
    }
}

// ---------------------------------------------------------------------------
// Kernel B (fused): pairwise attention + c_sum + projection + scatter + c_mol.
// grid (64, 4): (b, quarter of 16 i). 256 threads = 8 warps, 2 i per warp.
// j-loop split into two concurrent streams (j, j+32) -> 4 independent score
// chains per warp for latency hiding.
// dyn smem: region0[64*256] (u tile, then Wp) + region1[64*64] (c tile, then
//           csum 16x256, then reduction 16x64) = 80 KB -> 2 blocks/SM.
// ---------------------------------------------------------------------------
__global__ void __launch_bounds__(256, 2) kB(const float* __restrict__ inputs,
                                             const void* __restrict__ scope,
                                             const float* __restrict__ Wa_score,
                                             const float* __restrict__ Wp,
                                             float* __restrict__ d_out) {
    extern __shared__ float sm[];
    float* up_s  = sm;              // phase 1: u tile (P layout); phase 2: Wp
    float* cbp_s = sm + MA * E;     // phase 1: c tile (quad-swizzled); phase 2: csum
    __shared__ int flag;

    const bool is64 = scope_is64(scope);
    const int b = blockIdx.x, qq = blockIdx.y;
    const int t = threadIdx.x, l = t & 31, wid = t >> 5;

    // lane l owns e = l + 32k  (head n = l&3 lane-constant -> 3-shuffle reduce)
    float ws[8];
#pragma unroll
    for (int k = 0; k < 8; k++) ws[k] = __ldg(Wa_score + l + 32 * k);

    // stage u rows (P layout in gmem) via scope: float4 both sides
#pragma unroll
    for (int it = 0; it < 16; it++) {
        int Q = t + 256 * it;            // 64 rows * 64 quads
        int j = Q >> 6, qd = Q & 63;
        long long s = scope_at(scope, b * MA + j, is64);
        ((float4*)up_s)[Q] = ((const float4*)(g_u + (size_t)s * E))[qd];
    }
    // stage c: h-group h quad qA=2h+(h>=4) holds m=0..3, qB=2h+1-(h>=4) m=4..7
#pragma unroll
    for (int it = 0; it < 4; it++) {
        int Q = t + 256 * it;            // 64 rows * 16 quads
        int j = Q >> 4, qd = Q & 15;
        long long s = scope_at(scope, b * MA + j, is64);
        const float* src = inputs + (size_t)s * H;
        int h = qd >> 1;
        int mb = ((qd & 1) == (qd >> 3)) ? 0 : 4;
        float4 v;
        v.x = src[h + 8 * (mb + 0)];
        v.y = src[h + 8 * (mb + 1)];
        v.z = src[h + 8 * (mb + 2)];
        v.w = src[h + 8 * (mb + 3)];
        ((float4*)cbp_s)[Q] = v;
    }
    __syncthreads();

    const int hq = l >> 2;
    const int qA = 2 * hq + (hq >> 2);       // h>=4 -> +1
    const int qB = 2 * hq + 1 - (hq >> 2);
    const int i0 = qq * 16 + wid, i1 = i0 + 8;

    const float4* uiA = (const float4*)(up_s + i0 * E);
    float4 A0 = uiA[l], A1 = uiA[32 + l];
    const float4* uiB = (const float4*)(up_s + i1 * E);
    float4 B0 = uiB[l], B1 = uiB[32 + l];

    unsigned long long csAP[4] = {0, 0, 0, 0}, csBP[4] = {0, 0, 0, 0};
    unsigned long long csAQ[4] = {0, 0, 0, 0}, csBQ[4] = {0, 0, 0, 0};

#pragma unroll 2
    for (int j = 0; j < 32; j++) {
        const float4* urP = (const float4*)(up_s + j * E);
        const float4* urQ = (const float4*)(up_s + (j + 32) * E);
        float4 p0 = urP[l], p1 = urP[32 + l];
        float4 q0 = urQ[l], q1 = urQ[32 + l];
        float v, sAP0, sAP1, sBP0, sBP1, sAQ0, sAQ1, sBQ0, sBQ1;

        v = fmaxf(A0.x + p0.x, 0.f); sAP0 = v * ws[0];
        v = fmaxf(A0.y + p0.y, 0.f); sAP1 = v * ws[1];
        v = fmaxf(A0.z + p0.z, 0.f); sAP0 = fmaf(v, ws[2], sAP0);
        v = fmaxf(A0.w + p0.w, 0.f); sAP1 = fmaf(v, ws[3], sAP1);
        v = fmaxf(A1.x + p1.x, 0.f); sAP0 = fmaf(v, ws[4], sAP0);
        v = fmaxf(A1.y + p1.y, 0.f); sAP1 = fmaf(v, ws[5], sAP1);
        v = fmaxf(A1.z + p1.z, 0.f); sAP0 = fmaf(v, ws[6], sAP0);
        v = fmaxf(A1.w + p1.w, 0.f); sAP1 = fmaf(v, ws[7], sAP1);

        v = fmaxf(B0.x + p0.x, 0.f); sBP0 = v * ws[0];
        v = fmaxf(B0.y + p0.y, 0.f); sBP1 = v * ws[1];
        v = fmaxf(B0.z + p0.z, 0.f); sBP0 = fmaf(v, ws[2], sBP0);
        v = fmaxf(B0.w + p0.w, 0.f); sBP1 = fmaf(v, ws[3], sBP1);
        v = fmaxf(B1.x + p1.x, 0.f); sBP0 = fmaf(v, ws[4], sBP0);
        v = fmaxf(B1.y + p1.y, 0.f); sBP1 = fmaf(v, ws[5], sBP1);
        v = fmaxf(B1.z + p1.z, 0.f); sBP0 = fmaf(v, ws[6], sBP0);
        v = fmaxf(B1.w + p1.w, 0.f); sBP1 = fmaf(v, ws[7], sBP1);

        v = fmaxf(A0.x + q0.x, 0.f); sAQ0 = v * ws[0];
        v = fmaxf(A0.y + q0.y, 0.f); sAQ1 = v * ws[1];
        v = fmaxf(A0.z + q0.z, 0.f); sAQ0 = fmaf(v, ws[2], sAQ0);
        v = fmaxf(A0.w + q0.w, 0.f); sAQ1 = fmaf(v, ws[3], sAQ1);
        v = fmaxf(A1.x + q1.x, 0.f); sAQ0 = fmaf(v, ws[4], sAQ0);
        v = fmaxf(A1.y + q1.y, 0.f); sAQ1 = fmaf(v, ws[5], sAQ1);
        v = fmaxf(A1.z + q1.z, 0.f); sAQ0 = fmaf(v, ws[6], sAQ0);
        v = fmaxf(A1.w + q1.w, 0.f); sAQ1 = fmaf(v, ws[7], sAQ1);

        v = fmaxf(B0.x + q0.x, 0.f); sBQ0 = v * ws[0];
        v = fmaxf(B0.y + q0.y, 0.f); sBQ1 = v * ws[1];
        v = fmaxf(B0.z + q0.z, 0.f); sBQ0 = fmaf(v, ws[2], sBQ0);
        v = fmaxf(B0.w + q0.w, 0.f); sBQ1 = fmaf(v, ws[3], sBQ1);
        v = fmaxf(B1.x + q1.x, 0.f); sBQ0 = fmaf(v, ws[4], sBQ0);
        v = fmaxf(B1.y + q1.y, 0.f); sBQ1 = fmaf(v, ws[5], sBQ1);
        v = fmaxf(B1.z + q1.z, 0.f); sBQ0 = fmaf(v, ws[6], sBQ0);
        v = fmaxf(B1.w + q1.w, 0.f); sBQ1 = fmaf(v, ws[7], sBQ1);

        float sAP = sAP0 + sAP1, sBP = sBP0 + sBP1;
        float sAQ = sAQ0 + sAQ1, sBQ = sBQ0 + sBQ1;
        sAP += __shfl_xor_sync(0xffffffffu, sAP, 4);
        sBP += __shfl_xor_sync(0xffffffffu, sBP, 4);
        sAQ += __shfl_xor_sync(0xffffffffu, sAQ, 4);
        sBQ += __shfl_xor_sync(0xffffffffu, sBQ, 4);
        sAP += __shfl_xor_sync(0xffffffffu, sAP, 8);
        sBP += __shfl_xor_sync(0xffffffffu, sBP, 8);
        sAQ += __shfl_xor_sync(0xffffffffu, sAQ, 8);
        sBQ += __shfl_xor_sync(0xffffffffu, sBQ, 8);
        sAP += __shfl_xor_sync(0xffffffffu, sAP, 16);
        sBP += __shfl_xor_sync(0xffffffffu, sBP, 16);
        sAQ += __shfl_xor_sync(0xffffffffu, sAQ, 16);
        sBQ += __shfl_xor_sync(0xffffffffu, sBQ, 16);

        unsigned long long attAP = pack2(sigmoid_fast(sAP));
        unsigned long long attBP = pack2(sigmoid_fast(sBP));
        unsigned long long attAQ = pack2(sigmoid_fast(sAQ));
        unsigned long long attBQ = pack2(sigmoid_fast(sBQ));

        ulonglong2 cP01 = *(const ulonglong2*)(cbp_s + j * H + 4 * qA);
        ulonglong2 cP23 = *(const ulonglong2*)(cbp_s + j * H + 4 * qB);
        ulonglong2 cQ01 = *(const ulonglong2*)(cbp_s + (j + 32) * H + 4 * qA);
        ulonglong2 cQ23 = *(const ulonglong2*)(cbp_s + (j + 32) * H + 4 * qB);

        FMA2(csAP[0], attAP, cP01.x);  FMA2(csAP[1], attAP, cP01.y);
        FMA2(csAP[2], attAP, cP23.x);  FMA2(csAP[3], attAP, cP23.y);
        FMA2(csBP[0], attBP, cP01.x);  FMA2(csBP[1], attBP, cP01.y);
        FMA2(csBP[2], attBP, cP23.x);  FMA2(csBP[3], attBP, cP23.y);
        FMA2(csAQ[0], attAQ, cQ01.x);  FMA2(csAQ[1], attAQ, cQ01.y);
        FMA2(csAQ[2], attAQ, cQ23.x);  FMA2(csAQ[3], attAQ, cQ23.y);
        FMA2(csBQ[0], attBQ, cQ01.x);  FMA2(csBQ[1], attBQ, cQ01.y);
        FMA2(csBQ[2], attBQ, cQ23.x);  FMA2(csBQ[3], attBQ, cQ23.y);
    }

    unsigned long long csA[4], csB[4];
#pragma unroll
    for (int q = 0; q < 4; q++) {
        ADD2(csA[q], csAP[q], csAQ[q]);
        ADD2(csB[q], csBP[q], csBQ[q]);
    }

    // ---- phase 2: in-block projection ----
    __syncthreads();                 // everyone done reading up_s / cbp_s
    float* cs_s = cbp_s;             // 16 rows x 256, LOGICAL e' order
    // lane l holds csum element m (=0..7) -> logical e' = l + 32m
    {
        float* rowA = cs_s + wid * E;
        float* rowB = cs_s + (wid + 8) * E;
#pragma unroll
        for (int q = 0; q < 4; q++) {
            float2 fA = *(float2*)&csA[q];
            float2 fB = *(float2*)&csB[q];
            rowA[l + 32 * (2 * q)]     = fA.x;
            rowA[l + 32 * (2 * q + 1)] = fA.y;
            rowB[l + 32 * (2 * q)]     = fB.x;
            rowB[l + 32 * (2 * q + 1)] = fB.y;
        }
    }
    // stage Wp into the freed u region (straight copy, logical [e][h])
    float* wp_s = up_s;
#pragma unroll
    for (int it = 0; it < 16; it++)
        ((float4*)wp_s)[t + 256 * it] = __ldg(((const float4*)Wp) + t + 256 * it);
    __syncthreads();

    const int cg = t & 15, rg = t >> 4;   // 16 col-groups x 16 rows
    const int c0 = cg * 4;
    unsigned long long acc01 = 0, acc23 = 0;
#pragma unroll 4
    for (int e = 0; e < E; e++) {
        ulonglong2 w = *(const ulonglong2*)(wp_s + e * H + c0);
        unsigned long long cc = pack2(cs_s[rg * E + e]);
        FMA2(acc01, cc, w.x);  FMA2(acc23, cc, w.y);
    }

    // scatter flat rows: flat[scope[b*64+i]] = A[b,i]  (scope==0 -> pad, skip)
    float* flat = d_out + BS * H;
    {
        long long s = scope_at(scope, b * MA + qq * 16 + rg, is64);
        if (s > 0) {
            ulonglong2 o; o.x = acc01; o.y = acc23;
            *((ulonglong2*)(flat + s * H + c0)) = o;
        }
    }

    // ---- phase 3: molecule partial + deterministic last-block c_mol ----
    __syncthreads();                 // done reading cs_s -> reuse as 16x64 red
    {
        ulonglong2 o; o.x = acc01; o.y = acc23;
        *((ulonglong2*)(cs_s + rg * H + c0)) = o;
    }
    __syncthreads();
    if (t < H) {
        float s = 0.f;
#pragma unroll
        for (int g = 0; g < 16; g++) s += cs_s[g * H + t];
        g_molpart[(b * 4 + qq) * H + t] = s;
        __threadfence();             // make partial visible before counter bump
    }
    __syncthreads();
    if (t == 0) {
        int old = atomicAdd(&g_count[b], 1);
        flag = (old == 3);
    }
    __syncthreads();
    if (flag && t < H) {
        __threadfence();             // acquire side
        const float* mp = g_molpart + b * 4 * H + t;
        // fixed grouping -> bit-deterministic
        d_out[b * H + t] = (mp[0] + mp[H]) + (mp[2 * H] + mp[3 * H]);
    }
}

// ---------------------------------------------------------------------------
extern "C" void kernel_launch(void* const* d_in, const int* in_sizes, int n_in,
                              void* d_out, int out_size) {
    const float* inputs   = (const float*)d_in[0];
    const void*  scope    = d_in[1];
    // d_in[2] = scope_rev_tensor (unused: scatter via scope is its inverse)
    const float* Wa_pair  = (const float*)d_in[3];
    const float* Wa_score = (const float*)d_in[4];
    const float* Wp       = (const float*)d_in[5];
    float* out = (float*)d_out;

    const int n1 = in_sizes[0] / H;                            // N+1 flat rows
    const int smemA = (H * E + 8 * H) * (int)sizeof(float);    // 67584 B
    const int smemB = (MA * E + MA * H) * (int)sizeof(float);  // 81920 B
    cudaFuncSetAttribute(kA, cudaFuncAttributeMaxDynamicSharedMemorySize, smemA);
    cudaFuncSetAttribute(kB, cudaFuncAttributeMaxDynamicSharedMemorySize, smemB);

    kA<<<(n1 + 7) / 8, 256, smemA>>>(inputs, Wa_pair, n1, out);
    kB<<<dim3(BS, 4), 256, smemB>>>(inputs, scope, Wa_score, Wp, out);
}

// round 8
// speedup vs baseline: 1.1051x; 1.1051x over previous
#include <cuda_runtime.h>

#define H   64
#define NH  4
#define MA  64
#define BS  64
#define E   256    // H*NH
#define MAXROWS 4096

// scratch (device globals: no allocation allowed)
// P layout for E-vectors: element e (l=e&31, k=e>>5) stored at
//   p = (k>>2)*128 + 4*l + (k&3)
// -> lane l's 8 elements are two float4s at quads l and 32+l (conflict-free LDS).
__device__ float g_u[MAXROWS * E];
// csum partials: [mol][quarter q][slot = other quarter][row 0..15][E], P layout.
__device__ float g_part[BS * 4 * 4 * 16 * E];   // 16.8 MB, L2-resident
__device__ float g_molpart[BS * 4 * H];
__device__ int   g_count[BS];

// tile list: (a,b) quarters with a<=b
__device__ const int TILE_A[10] = {0,0,0,0,1,1,1,2,2,3};
__device__ const int TILE_B[10] = {0,1,2,3,1,2,3,2,3,3};

__device__ __forceinline__ long long scope_at(const void* sp, int i, bool is64) {
    return is64 ? ((const long long*)sp)[i] : (long long)((const int*)sp)[i];
}
__device__ __forceinline__ bool scope_is64(const void* sp) {
    // scope flat: [1, 2, ...]; int32 -> word1 == 2 ; int64 -> word1 == 0
    return ((const int*)sp)[1] == 0;
}
__device__ __forceinline__ float sigmoid_fast(float s) {
    float t;
    asm("tanh.approx.f32 %0, %1;" : "=f"(t) : "f"(0.5f * s));
    return fmaf(0.5f, t, 0.5f);
}
__device__ __forceinline__ unsigned long long pack2(float x) {
    unsigned r = __float_as_uint(x);
    unsigned long long o;
    asm("mov.b64 %0, {%1, %1};" : "=l"(o) : "r"(r));
    return o;
}
#define FMA2(acc, a, b) asm("fma.rn.f32x2 %0, %1, %2, %0;" : "+l"(acc) : "l"(a), "l"(b))

// ---------------------------------------------------------------------------
// Kernel A: u = inputs @ Wa_pair (all N+1 flat rows), P-layout store.
// 16 rows/block, Wa_pair staged in smem. Zeroes flat row 0 + counters.
// dyn smem: wa_s[64*256] + cs[16*64] = 68 KB
// ---------------------------------------------------------------------------
__global__ void __launch_bounds__(256) kA(const float* __restrict__ inputs,
                                          const float* __restrict__ Wa_pair,
                                          int n1, float* __restrict__ d_out) {
    extern __shared__ float sm[];
    float* wa_s = sm;            // 64 x 256
    float* cs   = sm + H * E;    // 16 x 64
    const int t = threadIdx.x, blk = blockIdx.x;

    if (blk == 0) {
        if (t < 16)
            ((float4*)(d_out + BS * H))[t] = make_float4(0.f, 0.f, 0.f, 0.f);
        if (t < BS) g_count[t] = 0;
    }

#pragma unroll
    for (int it = 0; it < 16; it++)
        ((float4*)wa_s)[t + 256 * it] = __ldg(((const float4*)Wa_pair) + t + 256 * it);

    {
        int r = blk * 16 + (t >> 4), q = t & 15;
        float4 z = make_float4(0.f, 0.f, 0.f, 0.f);
        ((float4*)cs)[t] = (r < n1) ? ((const float4*)(inputs + (size_t)r * H))[q] : z;
    }
    __syncthreads();

    const int eg = t & 63, rg = t >> 6;   // 4 e-cols, 4 rows per thread
    const int e0 = eg * 4;
    float4 acc[4];
#pragma unroll
    for (int m = 0; m < 4; m++) acc[m] = make_float4(0.f, 0.f, 0.f, 0.f);

#pragma unroll 4
    for (int h = 0; h < H; h++) {
        float4 w = *(const float4*)(wa_s + h * E + e0);
#pragma unroll
        for (int m = 0; m < 4; m++) {
            float c = cs[(rg * 4 + m) * H + h];
            acc[m].x = fmaf(c, w.x, acc[m].x);
            acc[m].y = fmaf(c, w.y, acc[m].y);
            acc[m].z = fmaf(c, w.z, acc[m].z);
            acc[m].w = fmaf(c, w.w, acc[m].w);
        }
    }

#pragma unroll
    for (int m = 0; m < 4; m++) {
        int rr = blk * 16 + rg * 4 + m;
        if (rr < n1) {
            float* dst = g_u + (size_t)rr * E;
            float a4[4] = {acc[m].x, acc[m].y, acc[m].z, acc[m].w};
#pragma unroll
            for (int c = 0; c < 4; c++) {
                int e = e0 + c;
                int l = e & 31, k = e >> 5;
                dst[(k >> 2) * 128 + 4 * l + (k & 3)] = a4[c];
            }
        }
    }
}

// ---------------------------------------------------------------------------
// Kernel B: symmetric quarter-tile attention.
// grid (64, 10): (molecule, tile (a<=b)). 256 threads = 8 warps, 2 i per warp.
// Off-diag tiles cache the 16x16x4 att tile in smem and replay it (phase 2)
// for the transposed csum side. Partials -> g_part[mol][q][slot].
// dyn smem: u_b[16*256] + c_a[16*64] + c_b[16*64] + att[16*16*4] = 28 KB.
// ---------------------------------------------------------------------------
__global__ void __launch_bounds__(256, 3) kB(const void* __restrict__ scope,
                                             const float* __restrict__ inputs,
                                             const float* __restrict__ Wa_score) {
    extern __shared__ float sm[];
    float* ub_s  = sm;                   // 16 x 256 (P layout)
    float* ca_s  = sm + 16 * E;          // 16 x 64 (quad-swizzled)
    float* cb_s  = ca_s + 16 * H;        // 16 x 64
    float* att_s = cb_s + 16 * H;        // [j 16][i 16][n 4]

    const bool is64 = scope_is64(scope);
    const int m = blockIdx.x, tile = blockIdx.y;
    const int a = TILE_A[tile], bq = TILE_B[tile];
    const bool diag = (a == bq);
    const int t = threadIdx.x, l = t & 31, wid = t >> 5;

    float ws[8];
#pragma unroll
    for (int k = 0; k < 8; k++) ws[k] = __ldg(Wa_score + l + 32 * k);

    // warp's own 2 i-rows of u straight from gmem (P layout)
    long long sIA = scope_at(scope, m * MA + a * 16 + wid, is64);
    long long sIB = scope_at(scope, m * MA + a * 16 + wid + 8, is64);
    const float4* uA = (const float4*)(g_u + (size_t)sIA * E);
    const float4* uB = (const float4*)(g_u + (size_t)sIB * E);
    float4 A0 = __ldg(uA + l), A1 = __ldg(uA + 32 + l);
    float4 B0 = __ldg(uB + l), B1 = __ldg(uB + 32 + l);

    // stage u_b (16 rows x 64 quads = 1024 float4)
#pragma unroll
    for (int it = 0; it < 4; it++) {
        int Q = t + 256 * it;
        int j = Q >> 6, qd = Q & 63;
        long long s = scope_at(scope, m * MA + bq * 16 + j, is64);
        ((float4*)ub_s)[Q] = ((const float4*)(g_u + (size_t)s * E))[qd];
    }
    // stage c_b and (off-diag) c_a: 16 rows x 16 quads, quad-swizzled
    {
        int j = t >> 4, qd = t & 15;
        int h = qd >> 1;
        int mb = ((qd & 1) == (qd >> 3)) ? 0 : 4;
        {
            long long s = scope_at(scope, m * MA + bq * 16 + j, is64);
            const float* src = inputs + (size_t)s * H;
            float4 v;
            v.x = src[h + 8 * (mb + 0)];
            v.y = src[h + 8 * (mb + 1)];
            v.z = src[h + 8 * (mb + 2)];
            v.w = src[h + 8 * (mb + 3)];
            ((float4*)cb_s)[t] = v;
        }
        if (!diag) {
            long long s = scope_at(scope, m * MA + a * 16 + j, is64);
            const float* src = inputs + (size_t)s * H;
            float4 v;
            v.x = src[h + 8 * (mb + 0)];
            v.y = src[h + 8 * (mb + 1)];
            v.z = src[h + 8 * (mb + 2)];
            v.w = src[h + 8 * (mb + 3)];
            ((float4*)ca_s)[t] = v;
        }
    }
    __syncthreads();

    const int hq = l >> 2;
    const int qA = 2 * hq + (hq >> 2);       // h>=4 -> +1
    const int qB = 2 * hq + 1 - (hq >> 2);

    unsigned long long csA[4] = {0, 0, 0, 0}, csB[4] = {0, 0, 0, 0};

    // ---- phase 1: scores vs b-quarter + a-side csum ----
#pragma unroll 2
    for (int j = 0; j < 16; j++) {
        const float4* ur = (const float4*)(ub_s + j * E);
        float4 a0 = ur[l], a1 = ur[32 + l];
        float v, sA0, sA1, sB0, sB1;
        v = fmaxf(A0.x + a0.x, 0.f); sA0 = v * ws[0];
        v = fmaxf(A0.y + a0.y, 0.f); sA1 = v * ws[1];
        v = fmaxf(A0.z + a0.z, 0.f); sA0 = fmaf(v, ws[2], sA0);
        v = fmaxf(A0.w + a0.w, 0.f); sA1 = fmaf(v, ws[3], sA1);
        v = fmaxf(A1.x + a1.x, 0.f); sA0 = fmaf(v, ws[4], sA0);
        v = fmaxf(A1.y + a1.y, 0.f); sA1 = fmaf(v, ws[5], sA1);
        v = fmaxf(A1.z + a1.z, 0.f); sA0 = fmaf(v, ws[6], sA0);
        v = fmaxf(A1.w + a1.w, 0.f); sA1 = fmaf(v, ws[7], sA1);

        v = fmaxf(B0.x + a0.x, 0.f); sB0 = v * ws[0];
        v = fmaxf(B0.y + a0.y, 0.f); sB1 = v * ws[1];
        v = fmaxf(B0.z + a0.z, 0.f); sB0 = fmaf(v, ws[2], sB0);
        v = fmaxf(B0.w + a0.w, 0.f); sB1 = fmaf(v, ws[3], sB1);
        v = fmaxf(B1.x + a1.x, 0.f); sB0 = fmaf(v, ws[4], sB0);
        v = fmaxf(B1.y + a1.y, 0.f); sB1 = fmaf(v, ws[5], sB1);
        v = fmaxf(B1.z + a1.z, 0.f); sB0 = fmaf(v, ws[6], sB0);
        v = fmaxf(B1.w + a1.w, 0.f); sB1 = fmaf(v, ws[7], sB1);

        float sA = sA0 + sA1, sB = sB0 + sB1;
        sA += __shfl_xor_sync(0xffffffffu, sA, 4);
        sB += __shfl_xor_sync(0xffffffffu, sB, 4);
        sA += __shfl_xor_sync(0xffffffffu, sA, 8);
        sB += __shfl_xor_sync(0xffffffffu, sB, 8);
        sA += __shfl_xor_sync(0xffffffffu, sA, 16);
        sB += __shfl_xor_sync(0xffffffffu, sB, 16);

        float attAf = sigmoid_fast(sA);
        float attBf = sigmoid_fast(sB);
        if (!diag) {                      // cache att tile for phase 2
            if (l < 4)       att_s[j * 64 + wid * 4 + l] = attAf;
            else if (l < 8)  att_s[j * 64 + (wid + 8) * 4 + (l - 4)] = attBf;
        }
        unsigned long long attA = pack2(attAf);
        unsigned long long attB = pack2(attBf);

        ulonglong2 c01 = *(const ulonglong2*)(cb_s + j * H + 4 * qA);
        ulonglong2 c23 = *(const ulonglong2*)(cb_s + j * H + 4 * qB);
        FMA2(csA[0], attA, c01.x);  FMA2(csA[1], attA, c01.y);
        FMA2(csA[2], attA, c23.x);  FMA2(csA[3], attA, c23.y);
        FMA2(csB[0], attB, c01.x);  FMA2(csB[1], attB, c01.y);
        FMA2(csB[2], attB, c23.x);  FMA2(csB[3], attB, c23.y);
    }

    // a-side partial: g_part[m][a][slot=bq], rows wid / wid+8, P layout
    {
        float* base = g_part + (((size_t)(m * 4 + a) * 4 + bq) * 16) * E;
        ulonglong2 v;
        float* oA = base + wid * E;
        v.x = csA[0]; v.y = csA[1]; *(ulonglong2*)(oA + 4 * l) = v;
        v.x = csA[2]; v.y = csA[3]; *(ulonglong2*)(oA + 128 + 4 * l) = v;
        float* oB = base + (wid + 8) * E;
        v.x = csB[0]; v.y = csB[1]; *(ulonglong2*)(oB + 4 * l) = v;
        v.x = csB[2]; v.y = csB[3]; *(ulonglong2*)(oB + 128 + 4 * l) = v;
    }

    if (diag) return;

    // ---- phase 2: replay att transposed -> b-side csum ----
    __syncthreads();                      // att tile complete
    unsigned long long cjA[4] = {0, 0, 0, 0}, cjB[4] = {0, 0, 0, 0};
    const int n = l & 3;
#pragma unroll 4
    for (int ai = 0; ai < 16; ai++) {
        float aA = att_s[wid * 64 + ai * 4 + n];         // att(i=ai, j=wid)
        float aB = att_s[(wid + 8) * 64 + ai * 4 + n];   // att(i=ai, j=wid+8)
        unsigned long long pA = pack2(aA), pB = pack2(aB);
        ulonglong2 c01 = *(const ulonglong2*)(ca_s + ai * H + 4 * qA);
        ulonglong2 c23 = *(const ulonglong2*)(ca_s + ai * H + 4 * qB);
        FMA2(cjA[0], pA, c01.x);  FMA2(cjA[1], pA, c01.y);
        FMA2(cjA[2], pA, c23.x);  FMA2(cjA[3], pA, c23.y);
        FMA2(cjB[0], pB, c01.x);  FMA2(cjB[1], pB, c01.y);
        FMA2(cjB[2], pB, c23.x);  FMA2(cjB[3], pB, c23.y);
    }
    // b-side partial: g_part[m][bq][slot=a]
    {
        float* base = g_part + (((size_t)(m * 4 + bq) * 4 + a) * 16) * E;
        ulonglong2 v;
        float* oA = base + wid * E;
        v.x = cjA[0]; v.y = cjA[1]; *(ulonglong2*)(oA + 4 * l) = v;
        v.x = cjA[2]; v.y = cjA[3]; *(ulonglong2*)(oA + 128 + 4 * l) = v;
        float* oB = base + (wid + 8) * E;
        v.x = cjB[0]; v.y = cjB[1]; *(ulonglong2*)(oB + 4 * l) = v;
        v.x = cjB[2]; v.y = cjB[3]; *(ulonglong2*)(oB + 128 + 4 * l) = v;
    }
}

// ---------------------------------------------------------------------------
// Kernel D: sum 4 partial slots (fixed order), project @ Wp, scatter flat,
// molecule partials + deterministic last-block c_mol.
// grid (64, 4): (mol, quarter). 256 threads; thread = 1 row x 4 cols.
// dyn smem: wp_s[256*64] (P-permuted rows) + cs_s[16*256] = 80 KB.
// ---------------------------------------------------------------------------
__global__ void __launch_bounds__(256) kD(const void* __restrict__ scope,
                                          const float* __restrict__ Wp,
                                          float* __restrict__ d_out) {
    extern __shared__ float sm[];
    float* wp_s = sm;            // 256 x 64, row p holds Wp row e(p)
    float* cs_s = sm + E * H;    // 16 x 256 (P layout)
    __shared__ int flag;

    const bool is64 = scope_is64(scope);
    const int m = blockIdx.x, q = blockIdx.y;
    const int t = threadIdx.x;

    // stage Wp P-permuted: p -> e = (r>>2) + 32*((r&3) + 4*(p>>7)), r = p&127
#pragma unroll
    for (int it = 0; it < 16; it++) {
        int qd = t + 256 * it;
        int p = qd >> 4, quad = qd & 15;
        int e = ((p & 127) >> 2) + 32 * (((p & 127) & 3) + 4 * (p >> 7));
        ((float4*)wp_s)[qd] = __ldg(((const float4*)Wp) + e * 16 + quad);
    }
    // sum 4 slots in fixed order -> cs_s
    {
        const float4* base = (const float4*)(g_part + ((size_t)(m * 4 + q) * 4 * 16) * E);
#pragma unroll
        for (int it = 0; it < 4; it++) {
            int idx = t + 256 * it;              // 1024 float4
            float4 s0 = __ldg(base + idx);
            float4 s1 = __ldg(base + 1024 + idx);
            float4 s2 = __ldg(base + 2048 + idx);
            float4 s3 = __ldg(base + 3072 + idx);
            float4 r;
            r.x = (s0.x + s1.x) + (s2.x + s3.x);
            r.y = (s0.y + s1.y) + (s2.y + s3.y);
            r.z = (s0.z + s1.z) + (s2.z + s3.z);
            r.w = (s0.w + s1.w) + (s2.w + s3.w);
            ((float4*)cs_s)[idx] = r;
        }
    }
    __syncthreads();

    const int cg = t & 15, rg = t >> 4;   // 16 col-groups x 16 rows
    const int c0 = cg * 4;
    unsigned long long acc01 = 0, acc23 = 0;
#pragma unroll 4
    for (int p = 0; p < E; p++) {
        ulonglong2 w = *(const ulonglong2*)(wp_s + p * H + c0);
        unsigned long long cc = pack2(cs_s[rg * E + p]);
        FMA2(acc01, cc, w.x);  FMA2(acc23, cc, w.y);
    }

    // scatter flat: flat[scope[m*64 + q*16 + rg]] = row  (scope==0 -> pad, skip)
    float* flat = d_out + BS * H;
    {
        long long s = scope_at(scope, m * MA + q * 16 + rg, is64);
        if (s > 0) {
            ulonglong2 o; o.x = acc01; o.y = acc23;
            *((ulonglong2*)(flat + s * H + c0)) = o;
        }
    }

    // molecule partial + deterministic last-block c_mol
    __syncthreads();                     // cs_s free -> 16x64 reduction buf
    {
        ulonglong2 o; o.x = acc01; o.y = acc23;
        *((ulonglong2*)(cs_s + rg * H + c0)) = o;
    }
    __syncthreads();
    if (t < H) {
        float s = 0.f;
#pragma unroll
        for (int g = 0; g < 16; g++) s += cs_s[g * H + t];
        g_molpart[(m * 4 + q) * H + t] = s;
        __threadfence();
    }
    __syncthreads();
    if (t == 0) {
        int old = atomicAdd(&g_count[m], 1);
        flag = (old == 3);
    }
    __syncthreads();
    if (flag && t < H) {
        __threadfence();
        const float* mp = g_molpart + m * 4 * H + t;
        d_out[m * H + t] = (mp[0] + mp[H]) + (mp[2 * H] + mp[3 * H]);
    }
}

// ---------------------------------------------------------------------------
extern "C" void kernel_launch(void* const* d_in, const int* in_sizes, int n_in,
                              void* d_out, int out_size) {
    const float* inputs   = (const float*)d_in[0];
    const void*  scope    = d_in[1];
    // d_in[2] = scope_rev_tensor (unused: scatter via scope is its inverse)
    const float* Wa_pair  = (const float*)d_in[3];
    const float* Wa_score = (const float*)d_in[4];
    const float* Wp       = (const float*)d_in[5];
    float* out = (float*)d_out;

    const int n1 = in_sizes[0] / H;                              // N+1 flat rows
    const int smemA = (H * E + 16 * H) * (int)sizeof(float);     // 69632 B
    const int smemB = (16 * E + 2 * 16 * H + 16 * 16 * 4) * (int)sizeof(float); // 28672 B
    const int smemD = (E * H + 16 * E) * (int)sizeof(float);     // 81920 B
    cudaFuncSetAttribute(kA, cudaFuncAttributeMaxDynamicSharedMemorySize, smemA);
    cudaFuncSetAttribute(kB, cudaFuncAttributeMaxDynamicSharedMemorySize, smemB);
    cudaFuncSetAttribute(kD, cudaFuncAttributeMaxDynamicSharedMemorySize, smemD);

    kA<<<(n1 + 15) / 16, 256, smemA>>>(inputs, Wa_pair, n1, out);
    kB<<<dim3(BS, 10), 256, smemB>>>(scope, inputs, Wa_score);
    kD<<<dim3(BS, 4), 256, smemD>>>(scope, Wp, out);
}